// round 14
// baseline (speedup 1.0000x reference)
#include <cuda_runtime.h>
#include <cuda_bf16.h>
#include <cuda_fp16.h>
#include <cstdint>

#define HEADS   16
#define S_LEN   2048
#define D_MODEL 1024
#define HD      64
#define BATCH   2
#define BH      (BATCH*HEADS)     // 32
#define R_SZ    257
#define WIN     128

// Scratch (allocation-free rule: device globals)
__device__ float    g_RP[BH * S_LEN * R_SZ];        // ~67 MB
__device__ uint32_t g_Xp[4096 * 1024];              // X  split bf16 hi|mid interleaved
__device__ uint32_t g_Wp[3072 * 1024];              // W  split
__device__ uint32_t g_Qh[BH * S_LEN * 32];          // bf16x2 Q hi   (rp kernel)
__device__ uint32_t g_Qm[BH * S_LEN * 32];          // bf16x2 Q mid  (rp kernel)
__device__ uint32_t g_Qf[BH * S_LEN * 32];          // fp16x2 Q      (attn)
__device__ uint32_t g_Kfh[BH * S_LEN * 32];         // fp16x2 K hi   (attn)
__device__ uint32_t g_Kfl[BH * S_LEN * 32];         // fp16x2 K lo
__device__ uint32_t g_Vfh[BH * S_LEN * 32];         // fp16x2 V hi
__device__ uint32_t g_Vfl[BH * S_LEN * 32];         // fp16x2 V lo
__device__ uint32_t g_Wrh[256 * 32];                // Wr rows 0..255 split (bf16)
__device__ uint32_t g_Wrm[256 * 32];

// ===========================================================================
// Helpers
// ===========================================================================
__device__ __forceinline__ uint32_t smem_u32(const void* p) {
    uint32_t a;
    asm("{ .reg .u64 t; cvta.to.shared.u64 t, %1; cvt.u32.u64 %0, t; }"
        : "=r"(a) : "l"(p));
    return a;
}
__device__ __forceinline__ void ldsm4(uint32_t* r, uint32_t a) {
    asm volatile("ldmatrix.sync.aligned.m8n8.x4.shared.b16 {%0,%1,%2,%3}, [%4];"
                 : "=r"(r[0]), "=r"(r[1]), "=r"(r[2]), "=r"(r[3]) : "r"(a));
}
__device__ __forceinline__ void ldsm4t(uint32_t* r, uint32_t a) {
    asm volatile("ldmatrix.sync.aligned.m8n8.x4.trans.shared.b16 {%0,%1,%2,%3}, [%4];"
                 : "=r"(r[0]), "=r"(r[1]), "=r"(r[2]), "=r"(r[3]) : "r"(a));
}
// bf16 mma (qkv, rp)
__device__ __forceinline__ void mma_bf(float* c, uint32_t a0, uint32_t a1,
                                       uint32_t a2, uint32_t a3,
                                       uint32_t b0, uint32_t b1) {
    asm volatile("mma.sync.aligned.m16n8k16.row.col.f32.bf16.bf16.f32 "
                 "{%0,%1,%2,%3}, {%4,%5,%6,%7}, {%8,%9}, {%0,%1,%2,%3};"
                 : "+f"(c[0]), "+f"(c[1]), "+f"(c[2]), "+f"(c[3])
                 : "r"(a0), "r"(a1), "r"(a2), "r"(a3), "r"(b0), "r"(b1));
}
// fp16 mma (attn)
__device__ __forceinline__ void mma_hf(float* c, uint32_t a0, uint32_t a1,
                                       uint32_t a2, uint32_t a3,
                                       uint32_t b0, uint32_t b1) {
    asm volatile("mma.sync.aligned.m16n8k16.row.col.f32.f16.f16.f32 "
                 "{%0,%1,%2,%3}, {%4,%5,%6,%7}, {%8,%9}, {%0,%1,%2,%3};"
                 : "+f"(c[0]), "+f"(c[1]), "+f"(c[2]), "+f"(c[3])
                 : "r"(a0), "r"(a1), "r"(a2), "r"(a3), "r"(b0), "r"(b1));
}
__device__ __forceinline__ uint32_t packbf(float lo, float hi) {
    uint32_t r;
    asm("cvt.rn.bf16x2.f32 %0, %1, %2;" : "=r"(r) : "f"(hi), "f"(lo));
    return r;
}
__device__ __forceinline__ float unlo(uint32_t p) { return __uint_as_float(p << 16); }
__device__ __forceinline__ float unhi(uint32_t p) { return __uint_as_float(p & 0xFFFF0000u); }

__device__ __forceinline__ uint32_t packhf(float lo, float hi) {
    uint32_t r;
    asm("cvt.rn.f16x2.f32 %0, %1, %2;" : "=r"(r) : "f"(hi), "f"(lo));
    return r;
}
__device__ __forceinline__ float2 unpackhf(uint32_t p) {
    __half2 h = *reinterpret_cast<__half2*>(&p);
    return __half22float2(h);          // .x = lo, .y = hi
}

__device__ __forceinline__ void cpa16(uint32_t dst, const void* src) {
    asm volatile("cp.async.cg.shared.global [%0], [%1], 16;"
                 :: "r"(dst), "l"(src) : "memory");
}
#define CP_COMMIT() asm volatile("cp.async.commit_group;" ::: "memory")
#define CP_WAIT(N)  asm volatile("cp.async.wait_group %0;" :: "n"(N) : "memory")

// 128-byte rows: swizzle = XOR bits[4:6] with (row&7)
__device__ __forceinline__ uint32_t sw_off(int row, int colb) {
    return (uint32_t)row * 128u + (((uint32_t)colb) ^ (((uint32_t)row & 7u) << 4));
}

// ===========================================================================
// Kernel 0a: split fp32 [rows x 1024] into interleaved bf16 hi|mid.
// ===========================================================================
__global__ __launch_bounds__(256)
void split_kernel(const float* __restrict__ src, uint32_t* __restrict__ dst, int n4) {
    int i = blockIdx.x * blockDim.x + threadIdx.x;
    if (i >= n4) return;
    int idx = i * 4;
    int row = idx >> 10, col = idx & 1023;
    float4 v = *(const float4*)(src + idx);
    int kb = col >> 5, cw = col & 31;
    int base = row * 1024 + kb * 32 + (cw >> 1);
    uint32_t h0 = packbf(v.x, v.y), h1 = packbf(v.z, v.w);
    uint32_t m0 = packbf(v.x - unlo(h0), v.y - unhi(h0));
    uint32_t m1 = packbf(v.z - unlo(h1), v.w - unhi(h1));
    dst[base]      = h0;  dst[base + 1]      = h1;
    dst[base + 16] = m0;  dst[base + 16 + 1] = m1;
}

// Kernel 0b: split Wr rows 0..255 into g_Wrh/g_Wrm (32 u32 per row).
__global__ __launch_bounds__(256)
void wr_split_kernel(const float* __restrict__ Wr) {
    int i = blockIdx.x * blockDim.x + threadIdx.x;   // u32 index
    if (i >= 256 * 32) return;
    int row = i >> 5, cp = i & 31;
    float2 v = *(const float2*)(Wr + row * 64 + cp * 2);
    uint32_t h = packbf(v.x, v.y);
    uint32_t m = packbf(v.x - unlo(h), v.y - unhi(h));
    g_Wrh[i] = h; g_Wrm[i] = m;
}

// ===========================================================================
// Kernel 1: QKV projection, bf16 3-term mma.  (R13 structure)
// Epilogue: Q -> bf16 hi/mid (rp) + fp16 (attn); K,V -> fp16 hi/lo (attn).
// ===========================================================================
#define QKV_SMEM_B (3 * 32768)

__global__ __launch_bounds__(256, 2)
void qkv_mma_kernel(const float* __restrict__ bias) {
    extern __shared__ char qsm[];
    const uint32_t base = smem_u32(qsm);

    const int tid = threadIdx.x;
    const int lane = tid & 31, wid = tid >> 5;
    const int bx = blockIdx.x % 24, by = blockIdx.x / 24;
    const int m0 = by * 128, n0 = bx * 128;
    const int lrow = lane & 15, lcolb = (lane >> 4) * 16;

    const int cr = tid >> 1;
    const int ch = tid & 1;
    const char* Asrc = (const char*)g_Xp + (size_t)(m0 + cr) * 4096 + ch * 64;
    const char* Bsrc = (const char*)g_Wp + (size_t)(n0 + cr) * 4096 + ch * 64;

    float c[16][4];
    #pragma unroll
    for (int i = 0; i < 16; i++)
        #pragma unroll
        for (int j = 0; j < 4; j++) c[i][j] = 0.f;

    auto copy_stage = [&](int kc, uint32_t stg) {
        const uint32_t As = stg, Bs = stg + 16384;
        #pragma unroll
        for (int q = 0; q < 4; q++) {
            const int colb = ch * 64 + q * 16;
            cpa16(As + sw_off(cr, colb), Asrc + (size_t)kc * 128 + q * 16);
            cpa16(Bs + sw_off(cr, colb), Bsrc + (size_t)kc * 128 + q * 16);
        }
    };

    copy_stage(0, base);
    CP_COMMIT();
    copy_stage(1, base + 32768);
    CP_COMMIT();

    const int arow = wid * 16 + lrow;

    int s_cur = 0, s_pf = 2;
    for (int kc = 0; kc < 32; kc++) {
        const uint32_t stg = base + (uint32_t)s_cur * 32768u;
        if (kc < 30) { CP_WAIT(1); } else { CP_WAIT(0); }
        __syncthreads();
        if (kc + 2 < 32) {
            copy_stage(kc + 2, base + (uint32_t)s_pf * 32768u);
            CP_COMMIT();
        }

        const uint32_t As = stg, Bs = stg + 16384;
        #pragma unroll
        for (int ks = 0; ks < 2; ks++) {
            const int hi_cb = ks * 32 + lcolb;
            const int mi_cb = 64 + ks * 32 + lcolb;
            uint32_t ah[4], am[4];
            ldsm4(ah, As + sw_off(arow, hi_cb));
            ldsm4(am, As + sw_off(arow, mi_cb));
            #pragma unroll
            for (int g4 = 0; g4 < 2; g4++) {
                uint32_t bb[4][4];
                #pragma unroll
                for (int nb = 0; nb < 4; nb++)
                    ldsm4(bb[nb], Bs + sw_off(g4 * 64 + nb * 16 + lrow, hi_cb));
                #pragma unroll
                for (int nb = 0; nb < 4; nb++) {
                    float* c0 = c[g4 * 8 + nb * 2];
                    float* c1 = c[g4 * 8 + nb * 2 + 1];
                    mma_bf(c0, ah[0], ah[1], ah[2], ah[3], bb[nb][0], bb[nb][2]);
                    mma_bf(c1, ah[0], ah[1], ah[2], ah[3], bb[nb][1], bb[nb][3]);
                    mma_bf(c0, am[0], am[1], am[2], am[3], bb[nb][0], bb[nb][2]);
                    mma_bf(c1, am[0], am[1], am[2], am[3], bb[nb][1], bb[nb][3]);
                }
                #pragma unroll
                for (int nb = 0; nb < 4; nb++)
                    ldsm4(bb[nb], Bs + sw_off(g4 * 64 + nb * 16 + lrow, mi_cb));
                #pragma unroll
                for (int nb = 0; nb < 4; nb++) {
                    float* c0 = c[g4 * 8 + nb * 2];
                    float* c1 = c[g4 * 8 + nb * 2 + 1];
                    mma_bf(c0, ah[0], ah[1], ah[2], ah[3], bb[nb][0], bb[nb][2]);
                    mma_bf(c1, ah[0], ah[1], ah[2], ah[3], bb[nb][1], bb[nb][3]);
                }
            }
        }
        s_cur = (s_cur == 2) ? 0 : s_cur + 1;
        s_pf  = (s_pf  == 2) ? 0 : s_pf  + 1;
    }

    // Epilogue
    const int g = lane >> 2, t = lane & 3;
    const int mr0 = m0 + wid * 16 + g;
    const int bb0 = mr0 >> 11, sp0 = mr0 & 2047;
    const int sp1 = (mr0 + 8) & 2047;
    #pragma unroll
    for (int f = 0; f < 16; f++) {
        const int n = n0 + (f >> 1) * 16 + (f & 1) * 8 + t * 2;
        const float2 bv = *(const float2*)(bias + n);
        const int head = n / 192;
        const int rem  = n - head * 192;
        const int type = rem >> 6;
        const int c64  = rem & 63;
        float* ci = c[f];
        const float v0 = ci[0] + bv.x, v1 = ci[1] + bv.y;
        const float v2 = ci[2] + bv.x, v3 = ci[3] + bv.y;
        const int row0 = (bb0 * HEADS + head) * S_LEN + sp0;
        const int row1 = (bb0 * HEADS + head) * S_LEN + sp1;
        const size_t p0 = (size_t)row0 * 32 + (c64 >> 1);
        const size_t p1 = (size_t)row1 * 32 + (c64 >> 1);
        // fp16 hi/lo (all types need hi; K/V need lo)
        const uint32_t f0 = packhf(v0, v1);
        const uint32_t f1 = packhf(v2, v3);
        if (type == 0) {
            // bf16 hi/mid for rp + fp16 for attn
            const uint32_t h0 = packbf(v0, v1);
            const uint32_t mm0 = packbf(v0 - unlo(h0), v1 - unhi(h0));
            const uint32_t h1 = packbf(v2, v3);
            const uint32_t mm1 = packbf(v2 - unlo(h1), v3 - unhi(h1));
            g_Qh[p0] = h0; g_Qm[p0] = mm0; g_Qf[p0] = f0;
            g_Qh[p1] = h1; g_Qm[p1] = mm1; g_Qf[p1] = f1;
        } else {
            float2 u0 = unpackhf(f0), u1 = unpackhf(f1);
            const uint32_t l0 = packhf(v0 - u0.x, v1 - u0.y);
            const uint32_t l1 = packhf(v2 - u1.x, v3 - u1.y);
            uint32_t* dh = (type == 1) ? g_Kfh : g_Vfh;
            uint32_t* dl = (type == 1) ? g_Kfl : g_Vfl;
            dh[p0] = f0; dl[p0] = l0;
            dh[p1] = f1; dl[p1] = l1;
        }
    }
}

// ===========================================================================
// Kernel 2: rp on tensor cores (bf16 3-term, unchanged).
// ===========================================================================
#define RP_SMEM_B (4 * 16384)   // Qh, Qm, Wh, Wm

__global__ __launch_bounds__(256, 2)
void rp_mma_kernel(const float* __restrict__ Wr, const float* __restrict__ br) {
    extern __shared__ char rsm[];
    const uint32_t base = smem_u32(rsm);
    const uint32_t Qh = base, Qm = base + 16384;
    const uint32_t Wh = base + 32768, Wm = base + 49152;
    __shared__ float w256[64];

    const int bx = blockIdx.x;
    const int bh = blockIdx.y;
    const int stile = bx >> 1, nhalf = bx & 1;
    const int q0 = stile * 128, ncol0 = nhalf * 128;

    const int tid = threadIdx.x;
    const int lane = tid & 31, wid = tid >> 5;
    const int wm = wid & 3, wn = wid >> 2;
    const int lrow = lane & 15, lcolb = (lane >> 4) * 16;

    {
        const int r = tid >> 1;
        const int j0c = (tid & 1) * 4;
        const size_t qrowb = (size_t)(bh * S_LEN + q0 + r) * 128;
        const size_t wrowb = (size_t)(ncol0 + r) * 128;
        #pragma unroll
        for (int q = 0; q < 4; q++) {
            const int cb = (j0c + q) * 16;
            const uint32_t so = sw_off(r, cb);
            cpa16(Qh + so, (const char*)g_Qh + qrowb + cb);
            cpa16(Qm + so, (const char*)g_Qm + qrowb + cb);
            cpa16(Wh + so, (const char*)g_Wrh + wrowb + cb);
            cpa16(Wm + so, (const char*)g_Wrm + wrowb + cb);
        }
    }
    if (tid < 64) w256[tid] = __ldg(Wr + 256 * 64 + tid);
    CP_COMMIT();
    CP_WAIT(0);
    __syncthreads();

    float c[2][8][4];
    #pragma unroll
    for (int mf = 0; mf < 2; mf++)
        #pragma unroll
        for (int nf = 0; nf < 8; nf++)
            #pragma unroll
            for (int j = 0; j < 4; j++) c[mf][nf][j] = 0.f;

    #pragma unroll
    for (int ks = 0; ks < 4; ks++) {
        const int colb = ks * 32 + lcolb;
        uint32_t ah[2][4], am[2][4], bb[4][4];
        #pragma unroll
        for (int mf = 0; mf < 2; mf++) {
            const int r = wm * 32 + mf * 16 + lrow;
            ldsm4(ah[mf], Qh + sw_off(r, colb));
            ldsm4(am[mf], Qm + sw_off(r, colb));
        }
        #pragma unroll
        for (int nb = 0; nb < 4; nb++)
            ldsm4(bb[nb], Wh + sw_off(wn * 64 + nb * 16 + lrow, colb));
        #pragma unroll
        for (int mf = 0; mf < 2; mf++)
            #pragma unroll
            for (int nb = 0; nb < 4; nb++) {
                mma_bf(c[mf][2 * nb],     ah[mf][0], ah[mf][1], ah[mf][2], ah[mf][3], bb[nb][0], bb[nb][2]);
                mma_bf(c[mf][2 * nb + 1], ah[mf][0], ah[mf][1], ah[mf][2], ah[mf][3], bb[nb][1], bb[nb][3]);
                mma_bf(c[mf][2 * nb],     am[mf][0], am[mf][1], am[mf][2], am[mf][3], bb[nb][0], bb[nb][2]);
                mma_bf(c[mf][2 * nb + 1], am[mf][0], am[mf][1], am[mf][2], am[mf][3], bb[nb][1], bb[nb][3]);
            }
        #pragma unroll
        for (int nb = 0; nb < 4; nb++)
            ldsm4(bb[nb], Wm + sw_off(wn * 64 + nb * 16 + lrow, colb));
        #pragma unroll
        for (int mf = 0; mf < 2; mf++)
            #pragma unroll
            for (int nb = 0; nb < 4; nb++) {
                mma_bf(c[mf][2 * nb],     ah[mf][0], ah[mf][1], ah[mf][2], ah[mf][3], bb[nb][0], bb[nb][2]);
                mma_bf(c[mf][2 * nb + 1], ah[mf][0], ah[mf][1], ah[mf][2], ah[mf][3], bb[nb][1], bb[nb][3]);
            }
    }

    const int g = lane >> 2, t = lane & 3;
    #pragma unroll
    for (int mf = 0; mf < 2; mf++) {
        const int r0g = q0 + wm * 32 + mf * 16 + g;
        const size_t rb0 = (size_t)(bh * S_LEN + r0g) * R_SZ;
        const size_t rb1 = (size_t)(bh * S_LEN + r0g + 8) * R_SZ;
        #pragma unroll
        for (int nf = 0; nf < 8; nf++) {
            const int col = ncol0 + wn * 64 + nf * 8 + t * 2;
            const float2 bv = *(const float2*)(br + col);
            g_RP[rb0 + col]     = c[mf][nf][0] + bv.x;
            g_RP[rb0 + col + 1] = c[mf][nf][1] + bv.y;
            g_RP[rb1 + col]     = c[mf][nf][2] + bv.x;
            g_RP[rb1 + col + 1] = c[mf][nf][3] + bv.y;
        }
    }

    if (nhalf == 0 && tid < 128) {
        const uint32_t* qh = g_Qh + (size_t)(bh * S_LEN + q0 + tid) * 32;
        const uint32_t* qm = g_Qm + (size_t)(bh * S_LEN + q0 + tid) * 32;
        float acc = 0.f;
        #pragma unroll
        for (int k = 0; k < 32; k++) {
            const uint32_t h = qh[k], m = qm[k];
            acc += (unlo(h) + unlo(m)) * w256[2 * k]
                 + (unhi(h) + unhi(m)) * w256[2 * k + 1];
        }
        g_RP[(size_t)(bh * S_LEN + q0 + tid) * R_SZ + 256] = acc + __ldg(br + 256);
    }
}

// ===========================================================================
// Kernel 3: flash attention, fp16 2-term (S: Qf*Kh+Qf*Kl; O: Ph*Vh+Ph*Vl).
// smem: Qf 16KB + 2 stages x {Kfh,Kfl,Vfh,Vfl 8K each} = 80KB.
// ===========================================================================
#define ATT_SMEM_B (16384 + 2 * 32768)

__global__ __launch_bounds__(256, 2)
void attn_mma_kernel(float* __restrict__ out) {
    extern __shared__ char asm_[];
    const uint32_t base = smem_u32(asm_);
    const uint32_t Qf = base;
    const uint32_t stg0 = base + 16384;

    const int qt = blockIdx.x, bh = blockIdx.y;
    const int q0 = qt * 128;
    const int tid = threadIdx.x;
    const int lane = tid & 31, wid = tid >> 5;
    const int g = lane >> 2, t = lane & 3;
    const int lrow = lane & 15, lcolb = (lane >> 4) * 16;

    {
        const int r = tid >> 1;
        const int j0c = (tid & 1) * 4;
        const size_t rowb = (size_t)(bh * S_LEN + q0 + r) * 128;
        #pragma unroll
        for (int q = 0; q < 4; q++)
            cpa16(Qf + sw_off(r, (j0c + q) * 16), (const char*)g_Qf + rowb + (j0c + q) * 16);
    }

    const int kvr = tid >> 2;
    const int kvj = (tid & 3) * 2;
    auto copy_kv = [&](int kb, uint32_t stg) {
        const size_t rowb = (size_t)(bh * S_LEN + kb + kvr) * 128;
        const uint32_t Ksh = stg, Ksl = stg + 8192, Vsh = stg + 16384, Vsl = stg + 24576;
        #pragma unroll
        for (int q = 0; q < 2; q++) {
            const int cb = (kvj + q) * 16;
            const uint32_t so = sw_off(kvr, cb);
            cpa16(Ksh + so, (const char*)g_Kfh + rowb + cb);
            cpa16(Ksl + so, (const char*)g_Kfl + rowb + cb);
            cpa16(Vsh + so, (const char*)g_Vfh + rowb + cb);
            cpa16(Vsl + so, (const char*)g_Vfl + rowb + cb);
        }
    };

    copy_kv(0, stg0);
    CP_COMMIT();

    float o[8][4];
    #pragma unroll
    for (int i = 0; i < 8; i++)
        #pragma unroll
        for (int j = 0; j < 4; j++) o[i][j] = 0.f;
    float macc[2] = {-1e30f, -1e30f};
    float lacc[2] = {0.f, 0.f};

    const int i0 = q0 + wid * 16 + g;
    const int i1 = i0 + 8;
    const float* rpb0 = g_RP + ((size_t)(bh * S_LEN + i0)) * R_SZ + WIN;
    const float* rpb1 = g_RP + ((size_t)(bh * S_LEN + i1)) * R_SZ + WIN;
    const float rLo0 = __ldg(rpb0 - WIN), rHi0 = __ldg(rpb0 + WIN);
    const float rLo1 = __ldg(rpb1 - WIN), rHi1 = __ldg(rpb1 + WIN);

    for (int jt = 0; jt < S_LEN / 64; jt++) {
        const int kb = jt * 64;
        const uint32_t stg = stg0 + (uint32_t)(jt & 1) * 32768;
        if (jt + 1 < S_LEN / 64) {
            copy_kv(kb + 64, stg0 + (uint32_t)((jt + 1) & 1) * 32768);
            CP_COMMIT();
            CP_WAIT(1);
        } else {
            CP_WAIT(0);
        }
        __syncthreads();

        const uint32_t Ksh = stg, Ksl = stg + 8192, Vsh = stg + 16384, Vsl = stg + 24576;

        // ---- S = Qf*Kh + Qf*Kl ----
        float s[8][4];
        #pragma unroll
        for (int i = 0; i < 8; i++)
            #pragma unroll
            for (int j = 0; j < 4; j++) s[i][j] = 0.f;

        #pragma unroll
        for (int ks = 0; ks < 4; ks++) {
            const int colb = ks * 32 + lcolb;
            uint32_t aq[4], bk[4][4];
            ldsm4(aq, Qf + sw_off(wid * 16 + lrow, colb));
            #pragma unroll
            for (int nb = 0; nb < 4; nb++)
                ldsm4(bk[nb], Ksh + sw_off(nb * 16 + lrow, colb));
            #pragma unroll
            for (int nb = 0; nb < 4; nb++) {
                mma_hf(s[2 * nb],     aq[0], aq[1], aq[2], aq[3], bk[nb][0], bk[nb][2]);
                mma_hf(s[2 * nb + 1], aq[0], aq[1], aq[2], aq[3], bk[nb][1], bk[nb][3]);
            }
            #pragma unroll
            for (int nb = 0; nb < 4; nb++)
                ldsm4(bk[nb], Ksl + sw_off(nb * 16 + lrow, colb));
            #pragma unroll
            for (int nb = 0; nb < 4; nb++) {
                mma_hf(s[2 * nb],     aq[0], aq[1], aq[2], aq[3], bk[nb][0], bk[nb][2]);
                mma_hf(s[2 * nb + 1], aq[0], aq[1], aq[2], aq[3], bk[nb][1], bk[nb][3]);
            }
        }

        // ---- scale + relative-position bias (clamped-tile fast path) ----
        {
            bool c0 = false, c1 = false;
            float b0 = 0.f, b1 = 0.f;
            if (kb + 63 - i0 <= -WIN)      { b0 = rLo0; c0 = true; }
            else if (kb - i0 >= WIN)       { b0 = rHi0; c0 = true; }
            if (kb + 63 - i1 <= -WIN)      { b1 = rLo1; c1 = true; }
            else if (kb - i1 >= WIN)       { b1 = rHi1; c1 = true; }
            if (c0 && c1) {
                #pragma unroll
                for (int nf = 0; nf < 8; nf++) {
                    s[nf][0] = fmaf(s[nf][0], 0.125f, b0);
                    s[nf][1] = fmaf(s[nf][1], 0.125f, b0);
                    s[nf][2] = fmaf(s[nf][2], 0.125f, b1);
                    s[nf][3] = fmaf(s[nf][3], 0.125f, b1);
                }
            } else {
                #pragma unroll
                for (int nf = 0; nf < 8; nf++) {
                    const int j = kb + nf * 8 + 2 * t;
                    int d0 = j - i0;       d0 = d0 < -WIN ? -WIN : (d0 > WIN ? WIN : d0);
                    int d0b = j + 1 - i0;  d0b = d0b < -WIN ? -WIN : (d0b > WIN ? WIN : d0b);
                    int d1 = j - i1;       d1 = d1 < -WIN ? -WIN : (d1 > WIN ? WIN : d1);
                    int d1b = j + 1 - i1;  d1b = d1b < -WIN ? -WIN : (d1b > WIN ? WIN : d1b);
                    s[nf][0] = s[nf][0] * 0.125f + __ldg(rpb0 + d0);
                    s[nf][1] = s[nf][1] * 0.125f + __ldg(rpb0 + d0b);
                    s[nf][2] = s[nf][2] * 0.125f + __ldg(rpb1 + d1);
                    s[nf][3] = s[nf][3] * 0.125f + __ldg(rpb1 + d1b);
                }
            }
        }

        // ---- online softmax ----
        float mx0 = -1e30f, mx1 = -1e30f;
        #pragma unroll
        for (int nf = 0; nf < 8; nf++) {
            mx0 = fmaxf(mx0, fmaxf(s[nf][0], s[nf][1]));
            mx1 = fmaxf(mx1, fmaxf(s[nf][2], s[nf][3]));
        }
        mx0 = fmaxf(mx0, __shfl_xor_sync(0xffffffffu, mx0, 1));
        mx0 = fmaxf(mx0, __shfl_xor_sync(0xffffffffu, mx0, 2));
        mx1 = fmaxf(mx1, __shfl_xor_sync(0xffffffffu, mx1, 1));
        mx1 = fmaxf(mx1, __shfl_xor_sync(0xffffffffu, mx1, 2));
        const float mn0 = fmaxf(macc[0], mx0);
        const float mn1 = fmaxf(macc[1], mx1);
        const float cr0 = __expf(macc[0] - mn0);
        const float cr1 = __expf(macc[1] - mn1);
        float sum0 = 0.f, sum1 = 0.f;
        #pragma unroll
        for (int nf = 0; nf < 8; nf++) {
            s[nf][0] = __expf(s[nf][0] - mn0);
            s[nf][1] = __expf(s[nf][1] - mn0);
            s[nf][2] = __expf(s[nf][2] - mn1);
            s[nf][3] = __expf(s[nf][3] - mn1);
            sum0 += s[nf][0] + s[nf][1];
            sum1 += s[nf][2] + s[nf][3];
        }
        sum0 += __shfl_xor_sync(0xffffffffu, sum0, 1);
        sum0 += __shfl_xor_sync(0xffffffffu, sum0, 2);
        sum1 += __shfl_xor_sync(0xffffffffu, sum1, 1);
        sum1 += __shfl_xor_sync(0xffffffffu, sum1, 2);
        lacc[0] = lacc[0] * cr0 + sum0;  macc[0] = mn0;
        lacc[1] = lacc[1] * cr1 + sum1;  macc[1] = mn1;
        #pragma unroll
        for (int nf = 0; nf < 8; nf++) {
            o[nf][0] *= cr0; o[nf][1] *= cr0;
            o[nf][2] *= cr1; o[nf][3] *= cr1;
        }

        // ---- P -> fp16 (hi only) ----
        uint32_t p0h[8], p1h[8];
        #pragma unroll
        for (int nf = 0; nf < 8; nf++) {
            p0h[nf] = packhf(s[nf][0], s[nf][1]);
            p1h[nf] = packhf(s[nf][2], s[nf][3]);
        }

        // ---- O += Ph*Vh + Ph*Vl ----
        #pragma unroll
        for (int kk = 0; kk < 4; kk++) {
            uint32_t bv[4][4];
            const int rowv = kk * 16 + lrow;
            const uint32_t a0 = p0h[2 * kk], a1 = p1h[2 * kk];
            const uint32_t a2 = p0h[2 * kk + 1], a3 = p1h[2 * kk + 1];
            #pragma unroll
            for (int nb = 0; nb < 4; nb++)
                ldsm4t(bv[nb], Vsh + sw_off(rowv, nb * 32 + lcolb));
            #pragma unroll
            for (int nb = 0; nb < 4; nb++) {
                mma_hf(o[2 * nb],     a0, a1, a2, a3, bv[nb][0], bv[nb][1]);
                mma_hf(o[2 * nb + 1], a0, a1, a2, a3, bv[nb][2], bv[nb][3]);
            }
            #pragma unroll
            for (int nb = 0; nb < 4; nb++)
                ldsm4t(bv[nb], Vsl + sw_off(rowv, nb * 32 + lcolb));
            #pragma unroll
            for (int nb = 0; nb < 4; nb++) {
                mma_hf(o[2 * nb],     a0, a1, a2, a3, bv[nb][0], bv[nb][1]);
                mma_hf(o[2 * nb + 1], a0, a1, a2, a3, bv[nb][2], bv[nb][3]);
            }
        }
        __syncthreads();
    }

    const float inv0 = 1.f / lacc[0];
    const float inv1 = 1.f / lacc[1];
    const int bb = bh >> 4, hh = bh & 15;
    #pragma unroll
    for (int nf = 0; nf < 8; nf++) {
        const int ch = hh * HD + nf * 8 + 2 * t;
        *(float2*)&out[((size_t)(bb * S_LEN + i0)) * D_MODEL + ch] =
            make_float2(o[nf][0] * inv0, o[nf][1] * inv0);
        *(float2*)&out[((size_t)(bb * S_LEN + i1)) * D_MODEL + ch] =
            make_float2(o[nf][2] * inv1, o[nf][3] * inv1);
    }
}

// ---------------------------------------------------------------------------
extern "C" void kernel_launch(void* const* d_in, const int* in_sizes, int n_in,
                              void* d_out, int out_size) {
    (void)in_sizes; (void)n_in; (void)out_size;
    const float* x    = (const float*)d_in[0];
    const float* Wqkv = (const float*)d_in[1];
    const float* bqkv = (const float*)d_in[2];
    const float* Wr   = (const float*)d_in[3];
    const float* br   = (const float*)d_in[4];
    float* out = (float*)d_out;

    uint32_t* xp; cudaGetSymbolAddress((void**)&xp, g_Xp);
    uint32_t* wp; cudaGetSymbolAddress((void**)&wp, g_Wp);
    split_kernel<<<(4096 * 1024 / 4 + 255) / 256, 256>>>(x, xp, 4096 * 1024 / 4);
    split_kernel<<<(3072 * 1024 / 4 + 255) / 256, 256>>>(Wqkv, wp, 3072 * 1024 / 4);
    wr_split_kernel<<<32, 256>>>(Wr);

    cudaFuncSetAttribute(qkv_mma_kernel, cudaFuncAttributeMaxDynamicSharedMemorySize,
                         QKV_SMEM_B);
    qkv_mma_kernel<<<768, 256, QKV_SMEM_B>>>(bqkv);

    cudaFuncSetAttribute(rp_mma_kernel, cudaFuncAttributeMaxDynamicSharedMemorySize,
                         RP_SMEM_B);
    dim3 g2(32, 32);
    rp_mma_kernel<<<g2, 256, RP_SMEM_B>>>(Wr, br);

    cudaFuncSetAttribute(attn_mma_kernel, cudaFuncAttributeMaxDynamicSharedMemorySize,
                         ATT_SMEM_B);
    dim3 g3(16, 32);
    attn_mma_kernel<<<g3, 256, ATT_SMEM_B>>>(out);
}

// round 16
// speedup vs baseline: 1.5509x; 1.5509x over previous
#include <cuda_runtime.h>
#include <cuda_bf16.h>
#include <cuda_fp16.h>
#include <cstdint>

#define HEADS   16
#define S_LEN   2048
#define D_MODEL 1024
#define HD      64
#define BATCH   2
#define BH      (BATCH*HEADS)     // 32
#define R_SZ    257
#define WIN     128

// Scratch (allocation-free rule: device globals)
__device__ float    g_RP[BH * S_LEN * R_SZ];        // ~67 MB
__device__ uint32_t g_Xp[4096 * 1024];              // X  split bf16 hi|mid interleaved
__device__ uint32_t g_Wp[3072 * 1024];              // W  split
__device__ uint32_t g_Qh[BH * S_LEN * 32];          // bf16x2 Q hi   (rp kernel)
__device__ uint32_t g_Qm[BH * S_LEN * 32];          // bf16x2 Q mid  (rp kernel)
__device__ uint32_t g_Qf[BH * S_LEN * 32];          // fp16x2 Q      (attn)
__device__ uint32_t g_Kfh[BH * S_LEN * 32];         // fp16x2 K hi   (attn)
__device__ uint32_t g_Kfl[BH * S_LEN * 32];         // fp16x2 K lo
__device__ uint32_t g_Vfh[BH * S_LEN * 32];         // fp16x2 V hi
__device__ uint32_t g_Vfl[BH * S_LEN * 32];         // fp16x2 V lo
__device__ uint32_t g_Wrh[256 * 32];                // Wr rows 0..255 split (bf16)
__device__ uint32_t g_Wrm[256 * 32];

// ===========================================================================
// Helpers
// ===========================================================================
__device__ __forceinline__ uint32_t smem_u32(const void* p) {
    uint32_t a;
    asm("{ .reg .u64 t; cvta.to.shared.u64 t, %1; cvt.u32.u64 %0, t; }"
        : "=r"(a) : "l"(p));
    return a;
}
__device__ __forceinline__ void ldsm4(uint32_t* r, uint32_t a) {
    asm volatile("ldmatrix.sync.aligned.m8n8.x4.shared.b16 {%0,%1,%2,%3}, [%4];"
                 : "=r"(r[0]), "=r"(r[1]), "=r"(r[2]), "=r"(r[3]) : "r"(a));
}
__device__ __forceinline__ void ldsm4t(uint32_t* r, uint32_t a) {
    asm volatile("ldmatrix.sync.aligned.m8n8.x4.trans.shared.b16 {%0,%1,%2,%3}, [%4];"
                 : "=r"(r[0]), "=r"(r[1]), "=r"(r[2]), "=r"(r[3]) : "r"(a));
}
// bf16 mma (qkv, rp)
__device__ __forceinline__ void mma_bf(float* c, uint32_t a0, uint32_t a1,
                                       uint32_t a2, uint32_t a3,
                                       uint32_t b0, uint32_t b1) {
    asm volatile("mma.sync.aligned.m16n8k16.row.col.f32.bf16.bf16.f32 "
                 "{%0,%1,%2,%3}, {%4,%5,%6,%7}, {%8,%9}, {%0,%1,%2,%3};"
                 : "+f"(c[0]), "+f"(c[1]), "+f"(c[2]), "+f"(c[3])
                 : "r"(a0), "r"(a1), "r"(a2), "r"(a3), "r"(b0), "r"(b1));
}
// fp16 mma (attn)
__device__ __forceinline__ void mma_hf(float* c, uint32_t a0, uint32_t a1,
                                       uint32_t a2, uint32_t a3,
                                       uint32_t b0, uint32_t b1) {
    asm volatile("mma.sync.aligned.m16n8k16.row.col.f32.f16.f16.f32 "
                 "{%0,%1,%2,%3}, {%4,%5,%6,%7}, {%8,%9}, {%0,%1,%2,%3};"
                 : "+f"(c[0]), "+f"(c[1]), "+f"(c[2]), "+f"(c[3])
                 : "r"(a0), "r"(a1), "r"(a2), "r"(a3), "r"(b0), "r"(b1));
}
__device__ __forceinline__ uint32_t packbf(float lo, float hi) {
    uint32_t r;
    asm("cvt.rn.bf16x2.f32 %0, %1, %2;" : "=r"(r) : "f"(hi), "f"(lo));
    return r;
}
__device__ __forceinline__ float unlo(uint32_t p) { return __uint_as_float(p << 16); }
__device__ __forceinline__ float unhi(uint32_t p) { return __uint_as_float(p & 0xFFFF0000u); }

__device__ __forceinline__ uint32_t packhf(float lo, float hi) {
    uint32_t r;
    asm("cvt.rn.f16x2.f32 %0, %1, %2;" : "=r"(r) : "f"(hi), "f"(lo));
    return r;
}
__device__ __forceinline__ float2 unpackhf(uint32_t p) {
    __half2 h = *reinterpret_cast<__half2*>(&p);
    return __half22float2(h);          // .x = lo, .y = hi
}

__device__ __forceinline__ void cpa16(uint32_t dst, const void* src) {
    asm volatile("cp.async.cg.shared.global [%0], [%1], 16;"
                 :: "r"(dst), "l"(src) : "memory");
}
#define CP_COMMIT() asm volatile("cp.async.commit_group;" ::: "memory")
#define CP_WAIT(N)  asm volatile("cp.async.wait_group %0;" :: "n"(N) : "memory")

// 128-byte rows: swizzle = XOR bits[4:6] with (row&7)
__device__ __forceinline__ uint32_t sw_off(int row, int colb) {
    return (uint32_t)row * 128u + (((uint32_t)colb) ^ (((uint32_t)row & 7u) << 4));
}

// ===========================================================================
// Kernel 0a: split fp32 [rows x 1024] into interleaved bf16 hi|mid.
// ===========================================================================
__global__ __launch_bounds__(256)
void split_kernel(const float* __restrict__ src, uint32_t* __restrict__ dst, int n4) {
    int i = blockIdx.x * blockDim.x + threadIdx.x;
    if (i >= n4) return;
    int idx = i * 4;
    int row = idx >> 10, col = idx & 1023;
    float4 v = *(const float4*)(src + idx);
    int kb = col >> 5, cw = col & 31;
    int base = row * 1024 + kb * 32 + (cw >> 1);
    uint32_t h0 = packbf(v.x, v.y), h1 = packbf(v.z, v.w);
    uint32_t m0 = packbf(v.x - unlo(h0), v.y - unhi(h0));
    uint32_t m1 = packbf(v.z - unlo(h1), v.w - unhi(h1));
    dst[base]      = h0;  dst[base + 1]      = h1;
    dst[base + 16] = m0;  dst[base + 16 + 1] = m1;
}

// Kernel 0b: split Wr rows 0..255 into g_Wrh/g_Wrm (32 u32 per row).
__global__ __launch_bounds__(256)
void wr_split_kernel(const float* __restrict__ Wr) {
    int i = blockIdx.x * blockDim.x + threadIdx.x;   // u32 index
    if (i >= 256 * 32) return;
    int row = i >> 5, cp = i & 31;
    float2 v = *(const float2*)(Wr + row * 64 + cp * 2);
    uint32_t h = packbf(v.x, v.y);
    uint32_t m = packbf(v.x - unlo(h), v.y - unhi(h));
    g_Wrh[i] = h; g_Wrm[i] = m;
}

// ===========================================================================
// Kernel 1: QKV projection, bf16 3-term mma.  (R13 structure)
// Epilogue: Q -> bf16 hi/mid (rp) + fp16 (attn); K,V -> fp16 hi/lo (attn).
// ===========================================================================
#define QKV_SMEM_B (3 * 32768)

__global__ __launch_bounds__(256, 2)
void qkv_mma_kernel(const float* __restrict__ bias) {
    extern __shared__ char qsm[];
    const uint32_t base = smem_u32(qsm);

    const int tid = threadIdx.x;
    const int lane = tid & 31, wid = tid >> 5;
    const int bx = blockIdx.x % 24, by = blockIdx.x / 24;
    const int m0 = by * 128, n0 = bx * 128;
    const int lrow = lane & 15, lcolb = (lane >> 4) * 16;

    const int cr = tid >> 1;
    const int ch = tid & 1;
    const char* Asrc = (const char*)g_Xp + (size_t)(m0 + cr) * 4096 + ch * 64;
    const char* Bsrc = (const char*)g_Wp + (size_t)(n0 + cr) * 4096 + ch * 64;

    float c[16][4];
    #pragma unroll
    for (int i = 0; i < 16; i++)
        #pragma unroll
        for (int j = 0; j < 4; j++) c[i][j] = 0.f;

    auto copy_stage = [&](int kc, uint32_t stg) {
        const uint32_t As = stg, Bs = stg + 16384;
        #pragma unroll
        for (int q = 0; q < 4; q++) {
            const int colb = ch * 64 + q * 16;
            cpa16(As + sw_off(cr, colb), Asrc + (size_t)kc * 128 + q * 16);
            cpa16(Bs + sw_off(cr, colb), Bsrc + (size_t)kc * 128 + q * 16);
        }
    };

    copy_stage(0, base);
    CP_COMMIT();
    copy_stage(1, base + 32768);
    CP_COMMIT();

    const int arow = wid * 16 + lrow;

    int s_cur = 0, s_pf = 2;
    for (int kc = 0; kc < 32; kc++) {
        const uint32_t stg = base + (uint32_t)s_cur * 32768u;
        if (kc < 30) { CP_WAIT(1); } else { CP_WAIT(0); }
        __syncthreads();
        if (kc + 2 < 32) {
            copy_stage(kc + 2, base + (uint32_t)s_pf * 32768u);
            CP_COMMIT();
        }

        const uint32_t As = stg, Bs = stg + 16384;
        #pragma unroll
        for (int ks = 0; ks < 2; ks++) {
            const int hi_cb = ks * 32 + lcolb;
            const int mi_cb = 64 + ks * 32 + lcolb;
            uint32_t ah[4], am[4];
            ldsm4(ah, As + sw_off(arow, hi_cb));
            ldsm4(am, As + sw_off(arow, mi_cb));
            #pragma unroll
            for (int g4 = 0; g4 < 2; g4++) {
                uint32_t bb[4][4];
                #pragma unroll
                for (int nb = 0; nb < 4; nb++)
                    ldsm4(bb[nb], Bs + sw_off(g4 * 64 + nb * 16 + lrow, hi_cb));
                #pragma unroll
                for (int nb = 0; nb < 4; nb++) {
                    float* c0 = c[g4 * 8 + nb * 2];
                    float* c1 = c[g4 * 8 + nb * 2 + 1];
                    mma_bf(c0, ah[0], ah[1], ah[2], ah[3], bb[nb][0], bb[nb][2]);
                    mma_bf(c1, ah[0], ah[1], ah[2], ah[3], bb[nb][1], bb[nb][3]);
                    mma_bf(c0, am[0], am[1], am[2], am[3], bb[nb][0], bb[nb][2]);
                    mma_bf(c1, am[0], am[1], am[2], am[3], bb[nb][1], bb[nb][3]);
                }
                #pragma unroll
                for (int nb = 0; nb < 4; nb++)
                    ldsm4(bb[nb], Bs + sw_off(g4 * 64 + nb * 16 + lrow, mi_cb));
                #pragma unroll
                for (int nb = 0; nb < 4; nb++) {
                    float* c0 = c[g4 * 8 + nb * 2];
                    float* c1 = c[g4 * 8 + nb * 2 + 1];
                    mma_bf(c0, ah[0], ah[1], ah[2], ah[3], bb[nb][0], bb[nb][2]);
                    mma_bf(c1, ah[0], ah[1], ah[2], ah[3], bb[nb][1], bb[nb][3]);
                }
            }
        }
        s_cur = (s_cur == 2) ? 0 : s_cur + 1;
        s_pf  = (s_pf  == 2) ? 0 : s_pf  + 1;
    }

    // Epilogue
    const int g = lane >> 2, t = lane & 3;
    const int mr0 = m0 + wid * 16 + g;
    const int bb0 = mr0 >> 11, sp0 = mr0 & 2047;
    const int sp1 = (mr0 + 8) & 2047;
    #pragma unroll
    for (int f = 0; f < 16; f++) {
        const int n = n0 + (f >> 1) * 16 + (f & 1) * 8 + t * 2;
        const float2 bv = *(const float2*)(bias + n);
        const int head = n / 192;
        const int rem  = n - head * 192;
        const int type = rem >> 6;
        const int c64  = rem & 63;
        float* ci = c[f];
        const float v0 = ci[0] + bv.x, v1 = ci[1] + bv.y;
        const float v2 = ci[2] + bv.x, v3 = ci[3] + bv.y;
        const int row0 = (bb0 * HEADS + head) * S_LEN + sp0;
        const int row1 = (bb0 * HEADS + head) * S_LEN + sp1;
        const size_t p0 = (size_t)row0 * 32 + (c64 >> 1);
        const size_t p1 = (size_t)row1 * 32 + (c64 >> 1);
        const uint32_t f0 = packhf(v0, v1);
        const uint32_t f1 = packhf(v2, v3);
        if (type == 0) {
            const uint32_t h0 = packbf(v0, v1);
            const uint32_t mm0 = packbf(v0 - unlo(h0), v1 - unhi(h0));
            const uint32_t h1 = packbf(v2, v3);
            const uint32_t mm1 = packbf(v2 - unlo(h1), v3 - unhi(h1));
            g_Qh[p0] = h0; g_Qm[p0] = mm0; g_Qf[p0] = f0;
            g_Qh[p1] = h1; g_Qm[p1] = mm1; g_Qf[p1] = f1;
        } else {
            float2 u0 = unpackhf(f0), u1 = unpackhf(f1);
            const uint32_t l0 = packhf(v0 - u0.x, v1 - u0.y);
            const uint32_t l1 = packhf(v2 - u1.x, v3 - u1.y);
            uint32_t* dh = (type == 1) ? g_Kfh : g_Vfh;
            uint32_t* dl = (type == 1) ? g_Kfl : g_Vfl;
            dh[p0] = f0; dl[p0] = l0;
            dh[p1] = f1; dl[p1] = l1;
        }
    }
}

// ===========================================================================
// Kernel 2: rp on tensor cores (bf16 3-term, unchanged).
// ===========================================================================
#define RP_SMEM_B (4 * 16384)   // Qh, Qm, Wh, Wm

__global__ __launch_bounds__(256, 2)
void rp_mma_kernel(const float* __restrict__ Wr, const float* __restrict__ br) {
    extern __shared__ char rsm[];
    const uint32_t base = smem_u32(rsm);
    const uint32_t Qh = base, Qm = base + 16384;
    const uint32_t Wh = base + 32768, Wm = base + 49152;
    __shared__ float w256[64];

    const int bx = blockIdx.x;
    const int bh = blockIdx.y;
    const int stile = bx >> 1, nhalf = bx & 1;
    const int q0 = stile * 128, ncol0 = nhalf * 128;

    const int tid = threadIdx.x;
    const int lane = tid & 31, wid = tid >> 5;
    const int wm = wid & 3, wn = wid >> 2;
    const int lrow = lane & 15, lcolb = (lane >> 4) * 16;

    {
        const int r = tid >> 1;
        const int j0c = (tid & 1) * 4;
        const size_t qrowb = (size_t)(bh * S_LEN + q0 + r) * 128;
        const size_t wrowb = (size_t)(ncol0 + r) * 128;
        #pragma unroll
        for (int q = 0; q < 4; q++) {
            const int cb = (j0c + q) * 16;
            const uint32_t so = sw_off(r, cb);
            cpa16(Qh + so, (const char*)g_Qh + qrowb + cb);
            cpa16(Qm + so, (const char*)g_Qm + qrowb + cb);
            cpa16(Wh + so, (const char*)g_Wrh + wrowb + cb);
            cpa16(Wm + so, (const char*)g_Wrm + wrowb + cb);
        }
    }
    if (tid < 64) w256[tid] = __ldg(Wr + 256 * 64 + tid);
    CP_COMMIT();
    CP_WAIT(0);
    __syncthreads();

    float c[2][8][4];
    #pragma unroll
    for (int mf = 0; mf < 2; mf++)
        #pragma unroll
        for (int nf = 0; nf < 8; nf++)
            #pragma unroll
            for (int j = 0; j < 4; j++) c[mf][nf][j] = 0.f;

    #pragma unroll
    for (int ks = 0; ks < 4; ks++) {
        const int colb = ks * 32 + lcolb;
        uint32_t ah[2][4], am[2][4], bb[4][4];
        #pragma unroll
        for (int mf = 0; mf < 2; mf++) {
            const int r = wm * 32 + mf * 16 + lrow;
            ldsm4(ah[mf], Qh + sw_off(r, colb));
            ldsm4(am[mf], Qm + sw_off(r, colb));
        }
        #pragma unroll
        for (int nb = 0; nb < 4; nb++)
            ldsm4(bb[nb], Wh + sw_off(wn * 64 + nb * 16 + lrow, colb));
        #pragma unroll
        for (int mf = 0; mf < 2; mf++)
            #pragma unroll
            for (int nb = 0; nb < 4; nb++) {
                mma_bf(c[mf][2 * nb],     ah[mf][0], ah[mf][1], ah[mf][2], ah[mf][3], bb[nb][0], bb[nb][2]);
                mma_bf(c[mf][2 * nb + 1], ah[mf][0], ah[mf][1], ah[mf][2], ah[mf][3], bb[nb][1], bb[nb][3]);
                mma_bf(c[mf][2 * nb],     am[mf][0], am[mf][1], am[mf][2], am[mf][3], bb[nb][0], bb[nb][2]);
                mma_bf(c[mf][2 * nb + 1], am[mf][0], am[mf][1], am[mf][2], am[mf][3], bb[nb][1], bb[nb][3]);
            }
        #pragma unroll
        for (int nb = 0; nb < 4; nb++)
            ldsm4(bb[nb], Wm + sw_off(wn * 64 + nb * 16 + lrow, colb));
        #pragma unroll
        for (int mf = 0; mf < 2; mf++)
            #pragma unroll
            for (int nb = 0; nb < 4; nb++) {
                mma_bf(c[mf][2 * nb],     ah[mf][0], ah[mf][1], ah[mf][2], ah[mf][3], bb[nb][0], bb[nb][2]);
                mma_bf(c[mf][2 * nb + 1], ah[mf][0], ah[mf][1], ah[mf][2], ah[mf][3], bb[nb][1], bb[nb][3]);
            }
    }

    const int g = lane >> 2, t = lane & 3;
    #pragma unroll
    for (int mf = 0; mf < 2; mf++) {
        const int r0g = q0 + wm * 32 + mf * 16 + g;
        const size_t rb0 = (size_t)(bh * S_LEN + r0g) * R_SZ;
        const size_t rb1 = (size_t)(bh * S_LEN + r0g + 8) * R_SZ;
        #pragma unroll
        for (int nf = 0; nf < 8; nf++) {
            const int col = ncol0 + wn * 64 + nf * 8 + t * 2;
            const float2 bv = *(const float2*)(br + col);
            g_RP[rb0 + col]     = c[mf][nf][0] + bv.x;
            g_RP[rb0 + col + 1] = c[mf][nf][1] + bv.y;
            g_RP[rb1 + col]     = c[mf][nf][2] + bv.x;
            g_RP[rb1 + col + 1] = c[mf][nf][3] + bv.y;
        }
    }

    if (nhalf == 0 && tid < 128) {
        const uint32_t* qh = g_Qh + (size_t)(bh * S_LEN + q0 + tid) * 32;
        const uint32_t* qm = g_Qm + (size_t)(bh * S_LEN + q0 + tid) * 32;
        float acc = 0.f;
        #pragma unroll
        for (int k = 0; k < 32; k++) {
            const uint32_t h = qh[k], m = qm[k];
            acc += (unlo(h) + unlo(m)) * w256[2 * k]
                 + (unhi(h) + unhi(m)) * w256[2 * k + 1];
        }
        g_RP[(size_t)(bh * S_LEN + q0 + tid) * R_SZ + 256] = acc + __ldg(br + 256);
    }
}

// ===========================================================================
// Kernel 3: flash attention, fp16 2-term (S: Qf*Kh+Qf*Kl; O: Ph*Vh+Ph*Vl).
// smem: Qf 16KB + 2 stages x {Kfh,Kfl,Vfh,Vfl 8K each} = 80KB.
// ===========================================================================
#define ATT_SMEM_B (16384 + 2 * 32768)

__global__ __launch_bounds__(256, 2)
void attn_mma_kernel(float* __restrict__ out) {
    extern __shared__ char asm_[];
    const uint32_t base = smem_u32(asm_);
    const uint32_t Qf = base;
    const uint32_t stg0 = base + 16384;

    const int qt = blockIdx.x, bh = blockIdx.y;
    const int q0 = qt * 128;
    const int tid = threadIdx.x;
    const int lane = tid & 31, wid = tid >> 5;
    const int g = lane >> 2, t = lane & 3;
    const int lrow = lane & 15, lcolb = (lane >> 4) * 16;

    {
        const int r = tid >> 1;
        const int j0c = (tid & 1) * 4;
        const size_t rowb = (size_t)(bh * S_LEN + q0 + r) * 128;
        #pragma unroll
        for (int q = 0; q < 4; q++)
            cpa16(Qf + sw_off(r, (j0c + q) * 16), (const char*)g_Qf + rowb + (j0c + q) * 16);
    }

    const int kvr = tid >> 2;
    const int kvj = (tid & 3) * 2;
    auto copy_kv = [&](int kb, uint32_t stg) {
        const size_t rowb = (size_t)(bh * S_LEN + kb + kvr) * 128;
        const uint32_t Ksh = stg, Ksl = stg + 8192, Vsh = stg + 16384, Vsl = stg + 24576;
        #pragma unroll
        for (int q = 0; q < 2; q++) {
            const int cb = (kvj + q) * 16;
            const uint32_t so = sw_off(kvr, cb);
            cpa16(Ksh + so, (const char*)g_Kfh + rowb + cb);
            cpa16(Ksl + so, (const char*)g_Kfl + rowb + cb);
            cpa16(Vsh + so, (const char*)g_Vfh + rowb + cb);
            cpa16(Vsl + so, (const char*)g_Vfl + rowb + cb);
        }
    };

    copy_kv(0, stg0);
    CP_COMMIT();

    float o[8][4];
    #pragma unroll
    for (int i = 0; i < 8; i++)
        #pragma unroll
        for (int j = 0; j < 4; j++) o[i][j] = 0.f;
    float macc[2] = {-1e30f, -1e30f};
    float lacc[2] = {0.f, 0.f};

    const int i0 = q0 + wid * 16 + g;
    const int i1 = i0 + 8;
    const float* rpb0 = g_RP + ((size_t)(bh * S_LEN + i0)) * R_SZ + WIN;
    const float* rpb1 = g_RP + ((size_t)(bh * S_LEN + i1)) * R_SZ + WIN;
    const float rLo0 = __ldg(rpb0 - WIN), rHi0 = __ldg(rpb0 + WIN);
    const float rLo1 = __ldg(rpb1 - WIN), rHi1 = __ldg(rpb1 + WIN);

    for (int jt = 0; jt < S_LEN / 64; jt++) {
        const int kb = jt * 64;
        const uint32_t stg = stg0 + (uint32_t)(jt & 1) * 32768;
        if (jt + 1 < S_LEN / 64) {
            copy_kv(kb + 64, stg0 + (uint32_t)((jt + 1) & 1) * 32768);
            CP_COMMIT();
            CP_WAIT(1);
        } else {
            CP_WAIT(0);
        }
        __syncthreads();

        const uint32_t Ksh = stg, Ksl = stg + 8192, Vsh = stg + 16384, Vsl = stg + 24576;

        // ---- S = Qf*Kh + Qf*Kl ----
        float s[8][4];
        #pragma unroll
        for (int i = 0; i < 8; i++)
            #pragma unroll
            for (int j = 0; j < 4; j++) s[i][j] = 0.f;

        #pragma unroll
        for (int ks = 0; ks < 4; ks++) {
            const int colb = ks * 32 + lcolb;
            uint32_t aq[4], bk[4][4];
            ldsm4(aq, Qf + sw_off(wid * 16 + lrow, colb));
            #pragma unroll
            for (int nb = 0; nb < 4; nb++)
                ldsm4(bk[nb], Ksh + sw_off(nb * 16 + lrow, colb));
            #pragma unroll
            for (int nb = 0; nb < 4; nb++) {
                mma_hf(s[2 * nb],     aq[0], aq[1], aq[2], aq[3], bk[nb][0], bk[nb][2]);
                mma_hf(s[2 * nb + 1], aq[0], aq[1], aq[2], aq[3], bk[nb][1], bk[nb][3]);
            }
            #pragma unroll
            for (int nb = 0; nb < 4; nb++)
                ldsm4(bk[nb], Ksl + sw_off(nb * 16 + lrow, colb));
            #pragma unroll
            for (int nb = 0; nb < 4; nb++) {
                mma_hf(s[2 * nb],     aq[0], aq[1], aq[2], aq[3], bk[nb][0], bk[nb][2]);
                mma_hf(s[2 * nb + 1], aq[0], aq[1], aq[2], aq[3], bk[nb][1], bk[nb][3]);
            }
        }

        // ---- scale + relative-position bias (clamped-tile fast path) ----
        {
            bool c0 = false, c1 = false;
            float b0 = 0.f, b1 = 0.f;
            if (kb + 63 - i0 <= -WIN)      { b0 = rLo0; c0 = true; }
            else if (kb - i0 >= WIN)       { b0 = rHi0; c0 = true; }
            if (kb + 63 - i1 <= -WIN)      { b1 = rLo1; c1 = true; }
            else if (kb - i1 >= WIN)       { b1 = rHi1; c1 = true; }
            if (c0 && c1) {
                #pragma unroll
                for (int nf = 0; nf < 8; nf++) {
                    s[nf][0] = fmaf(s[nf][0], 0.125f, b0);
                    s[nf][1] = fmaf(s[nf][1], 0.125f, b0);
                    s[nf][2] = fmaf(s[nf][2], 0.125f, b1);
                    s[nf][3] = fmaf(s[nf][3], 0.125f, b1);
                }
            } else {
                #pragma unroll
                for (int nf = 0; nf < 8; nf++) {
                    const int j = kb + nf * 8 + 2 * t;
                    int d0 = j - i0;       d0 = d0 < -WIN ? -WIN : (d0 > WIN ? WIN : d0);
                    int d0b = j + 1 - i0;  d0b = d0b < -WIN ? -WIN : (d0b > WIN ? WIN : d0b);
                    int d1 = j - i1;       d1 = d1 < -WIN ? -WIN : (d1 > WIN ? WIN : d1);
                    int d1b = j + 1 - i1;  d1b = d1b < -WIN ? -WIN : (d1b > WIN ? WIN : d1b);
                    s[nf][0] = s[nf][0] * 0.125f + __ldg(rpb0 + d0);
                    s[nf][1] = s[nf][1] * 0.125f + __ldg(rpb0 + d0b);
                    s[nf][2] = s[nf][2] * 0.125f + __ldg(rpb1 + d1);
                    s[nf][3] = s[nf][3] * 0.125f + __ldg(rpb1 + d1b);
                }
            }
        }

        // ---- online softmax ----
        float mx0 = -1e30f, mx1 = -1e30f;
        #pragma unroll
        for (int nf = 0; nf < 8; nf++) {
            mx0 = fmaxf(mx0, fmaxf(s[nf][0], s[nf][1]));
            mx1 = fmaxf(mx1, fmaxf(s[nf][2], s[nf][3]));
        }
        mx0 = fmaxf(mx0, __shfl_xor_sync(0xffffffffu, mx0, 1));
        mx0 = fmaxf(mx0, __shfl_xor_sync(0xffffffffu, mx0, 2));
        mx1 = fmaxf(mx1, __shfl_xor_sync(0xffffffffu, mx1, 1));
        mx1 = fmaxf(mx1, __shfl_xor_sync(0xffffffffu, mx1, 2));
        const float mn0 = fmaxf(macc[0], mx0);
        const float mn1 = fmaxf(macc[1], mx1);
        const float cr0 = __expf(macc[0] - mn0);
        const float cr1 = __expf(macc[1] - mn1);
        float sum0 = 0.f, sum1 = 0.f;
        #pragma unroll
        for (int nf = 0; nf < 8; nf++) {
            s[nf][0] = __expf(s[nf][0] - mn0);
            s[nf][1] = __expf(s[nf][1] - mn0);
            s[nf][2] = __expf(s[nf][2] - mn1);
            s[nf][3] = __expf(s[nf][3] - mn1);
            sum0 += s[nf][0] + s[nf][1];
            sum1 += s[nf][2] + s[nf][3];
        }
        sum0 += __shfl_xor_sync(0xffffffffu, sum0, 1);
        sum0 += __shfl_xor_sync(0xffffffffu, sum0, 2);
        sum1 += __shfl_xor_sync(0xffffffffu, sum1, 1);
        sum1 += __shfl_xor_sync(0xffffffffu, sum1, 2);
        lacc[0] = lacc[0] * cr0 + sum0;  macc[0] = mn0;
        lacc[1] = lacc[1] * cr1 + sum1;  macc[1] = mn1;
        #pragma unroll
        for (int nf = 0; nf < 8; nf++) {
            o[nf][0] *= cr0; o[nf][1] *= cr0;
            o[nf][2] *= cr1; o[nf][3] *= cr1;
        }

        // ---- P -> fp16 (hi only) ----
        uint32_t p0h[8], p1h[8];
        #pragma unroll
        for (int nf = 0; nf < 8; nf++) {
            p0h[nf] = packhf(s[nf][0], s[nf][1]);
            p1h[nf] = packhf(s[nf][2], s[nf][3]);
        }

        // ---- O += Ph*Vh + Ph*Vl ----
        #pragma unroll
        for (int kk = 0; kk < 4; kk++) {
            uint32_t bv[4][4];
            const int rowv = kk * 16 + lrow;
            const uint32_t a0 = p0h[2 * kk], a1 = p1h[2 * kk];
            const uint32_t a2 = p0h[2 * kk + 1], a3 = p1h[2 * kk + 1];
            #pragma unroll
            for (int nb = 0; nb < 4; nb++)
                ldsm4t(bv[nb], Vsh + sw_off(rowv, nb * 32 + lcolb));
            #pragma unroll
            for (int nb = 0; nb < 4; nb++) {
                mma_hf(o[2 * nb],     a0, a1, a2, a3, bv[nb][0], bv[nb][1]);
                mma_hf(o[2 * nb + 1], a0, a1, a2, a3, bv[nb][2], bv[nb][3]);
            }
            #pragma unroll
            for (int nb = 0; nb < 4; nb++)
                ldsm4t(bv[nb], Vsl + sw_off(rowv, nb * 32 + lcolb));
            #pragma unroll
            for (int nb = 0; nb < 4; nb++) {
                mma_hf(o[2 * nb],     a0, a1, a2, a3, bv[nb][0], bv[nb][1]);
                mma_hf(o[2 * nb + 1], a0, a1, a2, a3, bv[nb][2], bv[nb][3]);
            }
        }
        __syncthreads();
    }

    const float inv0 = 1.f / lacc[0];
    const float inv1 = 1.f / lacc[1];
    const int bb = bh >> 4, hh = bh & 15;
    #pragma unroll
    for (int nf = 0; nf < 8; nf++) {
        const int ch = hh * HD + nf * 8 + 2 * t;
        *(float2*)&out[((size_t)(bb * S_LEN + i0)) * D_MODEL + ch] =
            make_float2(o[nf][0] * inv0, o[nf][1] * inv0);
        *(float2*)&out[((size_t)(bb * S_LEN + i1)) * D_MODEL + ch] =
            make_float2(o[nf][2] * inv1, o[nf][3] * inv1);
    }
}

// ---------------------------------------------------------------------------
extern "C" void kernel_launch(void* const* d_in, const int* in_sizes, int n_in,
                              void* d_out, int out_size) {
    (void)in_sizes; (void)n_in; (void)out_size;
    const float* x    = (const float*)d_in[0];
    const float* Wqkv = (const float*)d_in[1];
    const float* bqkv = (const float*)d_in[2];
    const float* Wr   = (const float*)d_in[3];
    const float* br   = (const float*)d_in[4];
    float* out = (float*)d_out;

    uint32_t* xp; cudaGetSymbolAddress((void**)&xp, g_Xp);
    uint32_t* wp; cudaGetSymbolAddress((void**)&wp, g_Wp);
    split_kernel<<<(4096 * 1024 / 4 + 255) / 256, 256>>>(x, xp, 4096 * 1024 / 4);
    split_kernel<<<(3072 * 1024 / 4 + 255) / 256, 256>>>(Wqkv, wp, 3072 * 1024 / 4);
    wr_split_kernel<<<32, 256>>>(Wr);

    cudaFuncSetAttribute(qkv_mma_kernel, cudaFuncAttributeMaxDynamicSharedMemorySize,
                         QKV_SMEM_B);
    qkv_mma_kernel<<<768, 256, QKV_SMEM_B>>>(bqkv);

    cudaFuncSetAttribute(rp_mma_kernel, cudaFuncAttributeMaxDynamicSharedMemorySize,
                         RP_SMEM_B);
    dim3 g2(32, 32);
    rp_mma_kernel<<<g2, 256, RP_SMEM_B>>>(Wr, br);

    cudaFuncSetAttribute(attn_mma_kernel, cudaFuncAttributeMaxDynamicSharedMemorySize,
                         ATT_SMEM_B);
    dim3 g3(16, 32);
    attn_mma_kernel<<<g3, 256, ATT_SMEM_B>>>(out);
}

// round 17
// speedup vs baseline: 1.5679x; 1.0110x over previous
#include <cuda_runtime.h>
#include <cuda_bf16.h>
#include <cuda_fp16.h>
#include <cstdint>

#define HEADS   16
#define S_LEN   2048
#define D_MODEL 1024
#define HD      64
#define BATCH   2
#define BH      (BATCH*HEADS)     // 32
#define R_SZ    257
#define WIN     128
#define LOG2E   1.4426950408889634f

// Scratch (allocation-free rule: device globals)
__device__ float    g_RP[BH * S_LEN * R_SZ];        // ~67 MB
__device__ uint32_t g_Xp[4096 * 1024];              // X  split bf16 hi|mid interleaved
__device__ uint32_t g_Wp[3072 * 1024];              // W  split
__device__ uint32_t g_Qh[BH * S_LEN * 32];          // bf16x2 Q hi   (rp kernel)
__device__ uint32_t g_Qm[BH * S_LEN * 32];          // bf16x2 Q mid  (rp kernel)
__device__ uint32_t g_Qf[BH * S_LEN * 32];          // fp16x2 Q      (attn)
__device__ uint32_t g_Kfh[BH * S_LEN * 32];         // fp16x2 K hi   (attn)
__device__ uint32_t g_Kfl[BH * S_LEN * 32];         // fp16x2 K lo
__device__ uint32_t g_Vfh[BH * S_LEN * 32];         // fp16x2 V hi
__device__ uint32_t g_Vfl[BH * S_LEN * 32];         // fp16x2 V lo
__device__ uint32_t g_Wrh[256 * 32];                // Wr rows 0..255 split (bf16)
__device__ uint32_t g_Wrm[256 * 32];

// ===========================================================================
// Helpers
// ===========================================================================
__device__ __forceinline__ uint32_t smem_u32(const void* p) {
    uint32_t a;
    asm("{ .reg .u64 t; cvta.to.shared.u64 t, %1; cvt.u32.u64 %0, t; }"
        : "=r"(a) : "l"(p));
    return a;
}
__device__ __forceinline__ void ldsm4(uint32_t* r, uint32_t a) {
    asm volatile("ldmatrix.sync.aligned.m8n8.x4.shared.b16 {%0,%1,%2,%3}, [%4];"
                 : "=r"(r[0]), "=r"(r[1]), "=r"(r[2]), "=r"(r[3]) : "r"(a));
}
__device__ __forceinline__ void ldsm4t(uint32_t* r, uint32_t a) {
    asm volatile("ldmatrix.sync.aligned.m8n8.x4.trans.shared.b16 {%0,%1,%2,%3}, [%4];"
                 : "=r"(r[0]), "=r"(r[1]), "=r"(r[2]), "=r"(r[3]) : "r"(a));
}
// bf16 mma (qkv, rp)
__device__ __forceinline__ void mma_bf(float* c, uint32_t a0, uint32_t a1,
                                       uint32_t a2, uint32_t a3,
                                       uint32_t b0, uint32_t b1) {
    asm volatile("mma.sync.aligned.m16n8k16.row.col.f32.bf16.bf16.f32 "
                 "{%0,%1,%2,%3}, {%4,%5,%6,%7}, {%8,%9}, {%0,%1,%2,%3};"
                 : "+f"(c[0]), "+f"(c[1]), "+f"(c[2]), "+f"(c[3])
                 : "r"(a0), "r"(a1), "r"(a2), "r"(a3), "r"(b0), "r"(b1));
}
// fp16 mma (attn)
__device__ __forceinline__ void mma_hf(float* c, uint32_t a0, uint32_t a1,
                                       uint32_t a2, uint32_t a3,
                                       uint32_t b0, uint32_t b1) {
    asm volatile("mma.sync.aligned.m16n8k16.row.col.f32.f16.f16.f32 "
                 "{%0,%1,%2,%3}, {%4,%5,%6,%7}, {%8,%9}, {%0,%1,%2,%3};"
                 : "+f"(c[0]), "+f"(c[1]), "+f"(c[2]), "+f"(c[3])
                 : "r"(a0), "r"(a1), "r"(a2), "r"(a3), "r"(b0), "r"(b1));
}
__device__ __forceinline__ uint32_t packbf(float lo, float hi) {
    uint32_t r;
    asm("cvt.rn.bf16x2.f32 %0, %1, %2;" : "=r"(r) : "f"(hi), "f"(lo));
    return r;
}
__device__ __forceinline__ float unlo(uint32_t p) { return __uint_as_float(p << 16); }
__device__ __forceinline__ float unhi(uint32_t p) { return __uint_as_float(p & 0xFFFF0000u); }

__device__ __forceinline__ uint32_t packhf(float lo, float hi) {
    uint32_t r;
    asm("cvt.rn.f16x2.f32 %0, %1, %2;" : "=r"(r) : "f"(hi), "f"(lo));
    return r;
}
__device__ __forceinline__ float2 unpackhf(uint32_t p) {
    __half2 h = *reinterpret_cast<__half2*>(&p);
    return __half22float2(h);          // .x = lo, .y = hi
}
__device__ __forceinline__ uint32_t ex2_f16x2(uint32_t a) {
    uint32_t d;
    asm("ex2.approx.f16x2 %0, %1;" : "=r"(d) : "r"(a));
    return d;
}

__device__ __forceinline__ void cpa16(uint32_t dst, const void* src) {
    asm volatile("cp.async.cg.shared.global [%0], [%1], 16;"
                 :: "r"(dst), "l"(src) : "memory");
}
#define CP_COMMIT() asm volatile("cp.async.commit_group;" ::: "memory")
#define CP_WAIT(N)  asm volatile("cp.async.wait_group %0;" :: "n"(N) : "memory")

// 128-byte rows: swizzle = XOR bits[4:6] with (row&7)
__device__ __forceinline__ uint32_t sw_off(int row, int colb) {
    return (uint32_t)row * 128u + (((uint32_t)colb) ^ (((uint32_t)row & 7u) << 4));
}

// ===========================================================================
// Kernel 0a: split fp32 [rows x 1024] into interleaved bf16 hi|mid.
// ===========================================================================
__global__ __launch_bounds__(256)
void split_kernel(const float* __restrict__ src, uint32_t* __restrict__ dst, int n4) {
    int i = blockIdx.x * blockDim.x + threadIdx.x;
    if (i >= n4) return;
    int idx = i * 4;
    int row = idx >> 10, col = idx & 1023;
    float4 v = *(const float4*)(src + idx);
    int kb = col >> 5, cw = col & 31;
    int base = row * 1024 + kb * 32 + (cw >> 1);
    uint32_t h0 = packbf(v.x, v.y), h1 = packbf(v.z, v.w);
    uint32_t m0 = packbf(v.x - unlo(h0), v.y - unhi(h0));
    uint32_t m1 = packbf(v.z - unlo(h1), v.w - unhi(h1));
    dst[base]      = h0;  dst[base + 1]      = h1;
    dst[base + 16] = m0;  dst[base + 16 + 1] = m1;
}

// Kernel 0b: split Wr rows 0..255 into g_Wrh/g_Wrm (32 u32 per row).
__global__ __launch_bounds__(256)
void wr_split_kernel(const float* __restrict__ Wr) {
    int i = blockIdx.x * blockDim.x + threadIdx.x;   // u32 index
    if (i >= 256 * 32) return;
    int row = i >> 5, cp = i & 31;
    float2 v = *(const float2*)(Wr + row * 64 + cp * 2);
    uint32_t h = packbf(v.x, v.y);
    uint32_t m = packbf(v.x - unlo(h), v.y - unhi(h));
    g_Wrh[i] = h; g_Wrm[i] = m;
}

// ===========================================================================
// Kernel 1: QKV projection, bf16 3-term mma. Accumulator dependency
// distance >= 8 (all-hi pass, then all-mid pass).
// ===========================================================================
#define QKV_SMEM_B (3 * 32768)

__global__ __launch_bounds__(256, 2)
void qkv_mma_kernel(const float* __restrict__ bias) {
    extern __shared__ char qsm[];
    const uint32_t base = smem_u32(qsm);

    const int tid = threadIdx.x;
    const int lane = tid & 31, wid = tid >> 5;
    const int bx = blockIdx.x % 24, by = blockIdx.x / 24;
    const int m0 = by * 128, n0 = bx * 128;
    const int lrow = lane & 15, lcolb = (lane >> 4) * 16;

    const int cr = tid >> 1;
    const int ch = tid & 1;
    const char* Asrc = (const char*)g_Xp + (size_t)(m0 + cr) * 4096 + ch * 64;
    const char* Bsrc = (const char*)g_Wp + (size_t)(n0 + cr) * 4096 + ch * 64;

    float c[16][4];
    #pragma unroll
    for (int i = 0; i < 16; i++)
        #pragma unroll
        for (int j = 0; j < 4; j++) c[i][j] = 0.f;

    auto copy_stage = [&](int kc, uint32_t stg) {
        const uint32_t As = stg, Bs = stg + 16384;
        #pragma unroll
        for (int q = 0; q < 4; q++) {
            const int colb = ch * 64 + q * 16;
            cpa16(As + sw_off(cr, colb), Asrc + (size_t)kc * 128 + q * 16);
            cpa16(Bs + sw_off(cr, colb), Bsrc + (size_t)kc * 128 + q * 16);
        }
    };

    copy_stage(0, base);
    CP_COMMIT();
    copy_stage(1, base + 32768);
    CP_COMMIT();

    const int arow = wid * 16 + lrow;

    int s_cur = 0, s_pf = 2;
    for (int kc = 0; kc < 32; kc++) {
        const uint32_t stg = base + (uint32_t)s_cur * 32768u;
        if (kc < 30) { CP_WAIT(1); } else { CP_WAIT(0); }
        __syncthreads();
        if (kc + 2 < 32) {
            copy_stage(kc + 2, base + (uint32_t)s_pf * 32768u);
            CP_COMMIT();
        }

        const uint32_t As = stg, Bs = stg + 16384;
        #pragma unroll
        for (int ks = 0; ks < 2; ks++) {
            const int hi_cb = ks * 32 + lcolb;
            const int mi_cb = 64 + ks * 32 + lcolb;
            uint32_t ah[4], am[4];
            ldsm4(ah, As + sw_off(arow, hi_cb));
            ldsm4(am, As + sw_off(arow, mi_cb));
            #pragma unroll
            for (int g4 = 0; g4 < 2; g4++) {
                uint32_t bb[4][4];
                #pragma unroll
                for (int nb = 0; nb < 4; nb++)
                    ldsm4(bb[nb], Bs + sw_off(g4 * 64 + nb * 16 + lrow, hi_cb));
                // pass 1: ah x bb — 8 distinct accumulators
                #pragma unroll
                for (int nb = 0; nb < 4; nb++) {
                    mma_bf(c[g4 * 8 + nb * 2],     ah[0], ah[1], ah[2], ah[3], bb[nb][0], bb[nb][2]);
                    mma_bf(c[g4 * 8 + nb * 2 + 1], ah[0], ah[1], ah[2], ah[3], bb[nb][1], bb[nb][3]);
                }
                // pass 2: am x bb — distance 8 from pass 1
                #pragma unroll
                for (int nb = 0; nb < 4; nb++) {
                    mma_bf(c[g4 * 8 + nb * 2],     am[0], am[1], am[2], am[3], bb[nb][0], bb[nb][2]);
                    mma_bf(c[g4 * 8 + nb * 2 + 1], am[0], am[1], am[2], am[3], bb[nb][1], bb[nb][3]);
                }
                #pragma unroll
                for (int nb = 0; nb < 4; nb++)
                    ldsm4(bb[nb], Bs + sw_off(g4 * 64 + nb * 16 + lrow, mi_cb));
                // pass 3: ah x bb_mid — distance 8
                #pragma unroll
                for (int nb = 0; nb < 4; nb++) {
                    mma_bf(c[g4 * 8 + nb * 2],     ah[0], ah[1], ah[2], ah[3], bb[nb][0], bb[nb][2]);
                    mma_bf(c[g4 * 8 + nb * 2 + 1], ah[0], ah[1], ah[2], ah[3], bb[nb][1], bb[nb][3]);
                }
            }
        }
        s_cur = (s_cur == 2) ? 0 : s_cur + 1;
        s_pf  = (s_pf  == 2) ? 0 : s_pf  + 1;
    }

    // Epilogue
    const int g = lane >> 2, t = lane & 3;
    const int mr0 = m0 + wid * 16 + g;
    const int bb0 = mr0 >> 11, sp0 = mr0 & 2047;
    const int sp1 = (mr0 + 8) & 2047;
    #pragma unroll
    for (int f = 0; f < 16; f++) {
        const int n = n0 + (f >> 1) * 16 + (f & 1) * 8 + t * 2;
        const float2 bv = *(const float2*)(bias + n);
        const int head = n / 192;
        const int rem  = n - head * 192;
        const int type = rem >> 6;
        const int c64  = rem & 63;
        float* ci = c[f];
        const float v0 = ci[0] + bv.x, v1 = ci[1] + bv.y;
        const float v2 = ci[2] + bv.x, v3 = ci[3] + bv.y;
        const int row0 = (bb0 * HEADS + head) * S_LEN + sp0;
        const int row1 = (bb0 * HEADS + head) * S_LEN + sp1;
        const size_t p0 = (size_t)row0 * 32 + (c64 >> 1);
        const size_t p1 = (size_t)row1 * 32 + (c64 >> 1);
        const uint32_t f0 = packhf(v0, v1);
        const uint32_t f1 = packhf(v2, v3);
        if (type == 0) {
            const uint32_t h0 = packbf(v0, v1);
            const uint32_t mm0 = packbf(v0 - unlo(h0), v1 - unhi(h0));
            const uint32_t h1 = packbf(v2, v3);
            const uint32_t mm1 = packbf(v2 - unlo(h1), v3 - unhi(h1));
            g_Qh[p0] = h0; g_Qm[p0] = mm0; g_Qf[p0] = f0;
            g_Qh[p1] = h1; g_Qm[p1] = mm1; g_Qf[p1] = f1;
        } else {
            float2 u0 = unpackhf(f0), u1 = unpackhf(f1);
            const uint32_t l0 = packhf(v0 - u0.x, v1 - u0.y);
            const uint32_t l1 = packhf(v2 - u1.x, v3 - u1.y);
            uint32_t* dh = (type == 1) ? g_Kfh : g_Vfh;
            uint32_t* dl = (type == 1) ? g_Kfl : g_Vfl;
            dh[p0] = f0; dl[p0] = l0;
            dh[p1] = f1; dl[p1] = l1;
        }
    }
}

// ===========================================================================
// Kernel 2: rp on tensor cores (bf16 3-term); mma passes separated.
// ===========================================================================
#define RP_SMEM_B (4 * 16384)   // Qh, Qm, Wh, Wm

__global__ __launch_bounds__(256, 2)
void rp_mma_kernel(const float* __restrict__ Wr, const float* __restrict__ br) {
    extern __shared__ char rsm[];
    const uint32_t base = smem_u32(rsm);
    const uint32_t Qh = base, Qm = base + 16384;
    const uint32_t Wh = base + 32768, Wm = base + 49152;
    __shared__ float w256[64];

    const int bx = blockIdx.x;
    const int bh = blockIdx.y;
    const int stile = bx >> 1, nhalf = bx & 1;
    const int q0 = stile * 128, ncol0 = nhalf * 128;

    const int tid = threadIdx.x;
    const int lane = tid & 31, wid = tid >> 5;
    const int wm = wid & 3, wn = wid >> 2;
    const int lrow = lane & 15, lcolb = (lane >> 4) * 16;

    {
        const int r = tid >> 1;
        const int j0c = (tid & 1) * 4;
        const size_t qrowb = (size_t)(bh * S_LEN + q0 + r) * 128;
        const size_t wrowb = (size_t)(ncol0 + r) * 128;
        #pragma unroll
        for (int q = 0; q < 4; q++) {
            const int cb = (j0c + q) * 16;
            const uint32_t so = sw_off(r, cb);
            cpa16(Qh + so, (const char*)g_Qh + qrowb + cb);
            cpa16(Qm + so, (const char*)g_Qm + qrowb + cb);
            cpa16(Wh + so, (const char*)g_Wrh + wrowb + cb);
            cpa16(Wm + so, (const char*)g_Wrm + wrowb + cb);
        }
    }
    if (tid < 64) w256[tid] = __ldg(Wr + 256 * 64 + tid);
    CP_COMMIT();
    CP_WAIT(0);
    __syncthreads();

    float c[2][8][4];
    #pragma unroll
    for (int mf = 0; mf < 2; mf++)
        #pragma unroll
        for (int nf = 0; nf < 8; nf++)
            #pragma unroll
            for (int j = 0; j < 4; j++) c[mf][nf][j] = 0.f;

    #pragma unroll
    for (int ks = 0; ks < 4; ks++) {
        const int colb = ks * 32 + lcolb;
        uint32_t ah[2][4], am[2][4], bb[4][4];
        #pragma unroll
        for (int mf = 0; mf < 2; mf++) {
            const int r = wm * 32 + mf * 16 + lrow;
            ldsm4(ah[mf], Qh + sw_off(r, colb));
            ldsm4(am[mf], Qm + sw_off(r, colb));
        }
        #pragma unroll
        for (int nb = 0; nb < 4; nb++)
            ldsm4(bb[nb], Wh + sw_off(wn * 64 + nb * 16 + lrow, colb));
        #pragma unroll
        for (int mf = 0; mf < 2; mf++)
            #pragma unroll
            for (int nb = 0; nb < 4; nb++) {
                mma_bf(c[mf][2 * nb],     ah[mf][0], ah[mf][1], ah[mf][2], ah[mf][3], bb[nb][0], bb[nb][2]);
                mma_bf(c[mf][2 * nb + 1], ah[mf][0], ah[mf][1], ah[mf][2], ah[mf][3], bb[nb][1], bb[nb][3]);
            }
        #pragma unroll
        for (int mf = 0; mf < 2; mf++)
            #pragma unroll
            for (int nb = 0; nb < 4; nb++) {
                mma_bf(c[mf][2 * nb],     am[mf][0], am[mf][1], am[mf][2], am[mf][3], bb[nb][0], bb[nb][2]);
                mma_bf(c[mf][2 * nb + 1], am[mf][0], am[mf][1], am[mf][2], am[mf][3], bb[nb][1], bb[nb][3]);
            }
        #pragma unroll
        for (int nb = 0; nb < 4; nb++)
            ldsm4(bb[nb], Wm + sw_off(wn * 64 + nb * 16 + lrow, colb));
        #pragma unroll
        for (int mf = 0; mf < 2; mf++)
            #pragma unroll
            for (int nb = 0; nb < 4; nb++) {
                mma_bf(c[mf][2 * nb],     ah[mf][0], ah[mf][1], ah[mf][2], ah[mf][3], bb[nb][0], bb[nb][2]);
                mma_bf(c[mf][2 * nb + 1], ah[mf][0], ah[mf][1], ah[mf][2], ah[mf][3], bb[nb][1], bb[nb][3]);
            }
    }

    const int g = lane >> 2, t = lane & 3;
    #pragma unroll
    for (int mf = 0; mf < 2; mf++) {
        const int r0g = q0 + wm * 32 + mf * 16 + g;
        const size_t rb0 = (size_t)(bh * S_LEN + r0g) * R_SZ;
        const size_t rb1 = (size_t)(bh * S_LEN + r0g + 8) * R_SZ;
        #pragma unroll
        for (int nf = 0; nf < 8; nf++) {
            const int col = ncol0 + wn * 64 + nf * 8 + t * 2;
            const float2 bv = *(const float2*)(br + col);
            g_RP[rb0 + col]     = c[mf][nf][0] + bv.x;
            g_RP[rb0 + col + 1] = c[mf][nf][1] + bv.y;
            g_RP[rb1 + col]     = c[mf][nf][2] + bv.x;
            g_RP[rb1 + col + 1] = c[mf][nf][3] + bv.y;
        }
    }

    if (nhalf == 0 && tid < 128) {
        const uint32_t* qh = g_Qh + (size_t)(bh * S_LEN + q0 + tid) * 32;
        const uint32_t* qm = g_Qm + (size_t)(bh * S_LEN + q0 + tid) * 32;
        float acc = 0.f;
        #pragma unroll
        for (int k = 0; k < 32; k++) {
            const uint32_t h = qh[k], m = qm[k];
            acc += (unlo(h) + unlo(m)) * w256[2 * k]
                 + (unhi(h) + unhi(m)) * w256[2 * k + 1];
        }
        g_RP[(size_t)(bh * S_LEN + q0 + tid) * R_SZ + 256] = acc + __ldg(br + 256);
    }
}

// ===========================================================================
// Kernel 3: flash attention, fp16 2-term; exp via ex2.approx.f16x2;
// row-sum l as a tensor-core ones-column.
// ===========================================================================
#define ATT_SMEM_B (16384 + 2 * 32768)

__global__ __launch_bounds__(256, 2)
void attn_mma_kernel(float* __restrict__ out) {
    extern __shared__ char asm_[];
    const uint32_t base = smem_u32(asm_);
    const uint32_t Qf = base;
    const uint32_t stg0 = base + 16384;

    const int qt = blockIdx.x, bh = blockIdx.y;
    const int q0 = qt * 128;
    const int tid = threadIdx.x;
    const int lane = tid & 31, wid = tid >> 5;
    const int g = lane >> 2, t = lane & 3;
    const int lrow = lane & 15, lcolb = (lane >> 4) * 16;

    {
        const int r = tid >> 1;
        const int j0c = (tid & 1) * 4;
        const size_t rowb = (size_t)(bh * S_LEN + q0 + r) * 128;
        #pragma unroll
        for (int q = 0; q < 4; q++)
            cpa16(Qf + sw_off(r, (j0c + q) * 16), (const char*)g_Qf + rowb + (j0c + q) * 16);
    }

    const int kvr = tid >> 2;
    const int kvj = (tid & 3) * 2;
    auto copy_kv = [&](int kb, uint32_t stg) {
        const size_t rowb = (size_t)(bh * S_LEN + kb + kvr) * 128;
        const uint32_t Ksh = stg, Ksl = stg + 8192, Vsh = stg + 16384, Vsl = stg + 24576;
        #pragma unroll
        for (int q = 0; q < 2; q++) {
            const int cb = (kvj + q) * 16;
            const uint32_t so = sw_off(kvr, cb);
            cpa16(Ksh + so, (const char*)g_Kfh + rowb + cb);
            cpa16(Ksl + so, (const char*)g_Kfl + rowb + cb);
            cpa16(Vsh + so, (const char*)g_Vfh + rowb + cb);
            cpa16(Vsl + so, (const char*)g_Vfl + rowb + cb);
        }
    };

    copy_kv(0, stg0);
    CP_COMMIT();

    float o[8][4], o_sum[4];
    #pragma unroll
    for (int i = 0; i < 8; i++)
        #pragma unroll
        for (int j = 0; j < 4; j++) o[i][j] = 0.f;
    #pragma unroll
    for (int j = 0; j < 4; j++) o_sum[j] = 0.f;
    float macc[2] = {-1e30f, -1e30f};

    const int i0 = q0 + wid * 16 + g;
    const int i1 = i0 + 8;
    const float* rpb0 = g_RP + ((size_t)(bh * S_LEN + i0)) * R_SZ + WIN;
    const float* rpb1 = g_RP + ((size_t)(bh * S_LEN + i1)) * R_SZ + WIN;
    const float rLo0 = __ldg(rpb0 - WIN), rHi0 = __ldg(rpb0 + WIN);
    const float rLo1 = __ldg(rpb1 - WIN), rHi1 = __ldg(rpb1 + WIN);
    const uint32_t ONESH = 0x3C003C00u;   // fp16x2 {1, 1}

    for (int jt = 0; jt < S_LEN / 64; jt++) {
        const int kb = jt * 64;
        const uint32_t stg = stg0 + (uint32_t)(jt & 1) * 32768;
        if (jt + 1 < S_LEN / 64) {
            copy_kv(kb + 64, stg0 + (uint32_t)((jt + 1) & 1) * 32768);
            CP_COMMIT();
            CP_WAIT(1);
        } else {
            CP_WAIT(0);
        }
        __syncthreads();

        const uint32_t Ksh = stg, Ksl = stg + 8192, Vsh = stg + 16384, Vsl = stg + 24576;

        // ---- S = Qf*Kh + Qf*Kl ----
        float s[8][4];
        #pragma unroll
        for (int i = 0; i < 8; i++)
            #pragma unroll
            for (int j = 0; j < 4; j++) s[i][j] = 0.f;

        #pragma unroll
        for (int ks = 0; ks < 4; ks++) {
            const int colb = ks * 32 + lcolb;
            uint32_t aq[4], bk[4][4];
            ldsm4(aq, Qf + sw_off(wid * 16 + lrow, colb));
            #pragma unroll
            for (int nb = 0; nb < 4; nb++)
                ldsm4(bk[nb], Ksh + sw_off(nb * 16 + lrow, colb));
            #pragma unroll
            for (int nb = 0; nb < 4; nb++) {
                mma_hf(s[2 * nb],     aq[0], aq[1], aq[2], aq[3], bk[nb][0], bk[nb][2]);
                mma_hf(s[2 * nb + 1], aq[0], aq[1], aq[2], aq[3], bk[nb][1], bk[nb][3]);
            }
            #pragma unroll
            for (int nb = 0; nb < 4; nb++)
                ldsm4(bk[nb], Ksl + sw_off(nb * 16 + lrow, colb));
            #pragma unroll
            for (int nb = 0; nb < 4; nb++) {
                mma_hf(s[2 * nb],     aq[0], aq[1], aq[2], aq[3], bk[nb][0], bk[nb][2]);
                mma_hf(s[2 * nb + 1], aq[0], aq[1], aq[2], aq[3], bk[nb][1], bk[nb][3]);
            }
        }

        // ---- scale + relative-position bias (clamped-tile fast path) ----
        {
            bool c0 = false, c1 = false;
            float b0 = 0.f, b1 = 0.f;
            if (kb + 63 - i0 <= -WIN)      { b0 = rLo0; c0 = true; }
            else if (kb - i0 >= WIN)       { b0 = rHi0; c0 = true; }
            if (kb + 63 - i1 <= -WIN)      { b1 = rLo1; c1 = true; }
            else if (kb - i1 >= WIN)       { b1 = rHi1; c1 = true; }
            if (c0 && c1) {
                #pragma unroll
                for (int nf = 0; nf < 8; nf++) {
                    s[nf][0] = fmaf(s[nf][0], 0.125f, b0);
                    s[nf][1] = fmaf(s[nf][1], 0.125f, b0);
                    s[nf][2] = fmaf(s[nf][2], 0.125f, b1);
                    s[nf][3] = fmaf(s[nf][3], 0.125f, b1);
                }
            } else {
                #pragma unroll
                for (int nf = 0; nf < 8; nf++) {
                    const int j = kb + nf * 8 + 2 * t;
                    int d0 = j - i0;       d0 = d0 < -WIN ? -WIN : (d0 > WIN ? WIN : d0);
                    int d0b = j + 1 - i0;  d0b = d0b < -WIN ? -WIN : (d0b > WIN ? WIN : d0b);
                    int d1 = j - i1;       d1 = d1 < -WIN ? -WIN : (d1 > WIN ? WIN : d1);
                    int d1b = j + 1 - i1;  d1b = d1b < -WIN ? -WIN : (d1b > WIN ? WIN : d1b);
                    s[nf][0] = s[nf][0] * 0.125f + __ldg(rpb0 + d0);
                    s[nf][1] = s[nf][1] * 0.125f + __ldg(rpb0 + d0b);
                    s[nf][2] = s[nf][2] * 0.125f + __ldg(rpb1 + d1);
                    s[nf][3] = s[nf][3] * 0.125f + __ldg(rpb1 + d1b);
                }
            }
        }

        // ---- online softmax: max, then exp via ex2.approx.f16x2 ----
        float mx0 = -1e30f, mx1 = -1e30f;
        #pragma unroll
        for (int nf = 0; nf < 8; nf++) {
            mx0 = fmaxf(mx0, fmaxf(s[nf][0], s[nf][1]));
            mx1 = fmaxf(mx1, fmaxf(s[nf][2], s[nf][3]));
        }
        mx0 = fmaxf(mx0, __shfl_xor_sync(0xffffffffu, mx0, 1));
        mx0 = fmaxf(mx0, __shfl_xor_sync(0xffffffffu, mx0, 2));
        mx1 = fmaxf(mx1, __shfl_xor_sync(0xffffffffu, mx1, 1));
        mx1 = fmaxf(mx1, __shfl_xor_sync(0xffffffffu, mx1, 2));
        const float mn0 = fmaxf(macc[0], mx0);
        const float mn1 = fmaxf(macc[1], mx1);
        const float cr0 = __expf(macc[0] - mn0);
        const float cr1 = __expf(macc[1] - mn1);
        macc[0] = mn0;  macc[1] = mn1;
        const float mnl0 = mn0 * LOG2E;
        const float mnl1 = mn1 * LOG2E;

        // P = 2^( s*log2e - mn*log2e )  computed pairwise in fp16
        uint32_t p0h[8], p1h[8];
        #pragma unroll
        for (int nf = 0; nf < 8; nf++) {
            const float a0 = fmaf(s[nf][0], LOG2E, -mnl0);
            const float a1 = fmaf(s[nf][1], LOG2E, -mnl0);
            const float a2 = fmaf(s[nf][2], LOG2E, -mnl1);
            const float a3 = fmaf(s[nf][3], LOG2E, -mnl1);
            p0h[nf] = ex2_f16x2(packhf(a0, a1));
            p1h[nf] = ex2_f16x2(packhf(a2, a3));
        }

        // rescale O and the l-column
        #pragma unroll
        for (int nf = 0; nf < 8; nf++) {
            o[nf][0] *= cr0; o[nf][1] *= cr0;
            o[nf][2] *= cr1; o[nf][3] *= cr1;
        }
        o_sum[0] *= cr0; o_sum[1] *= cr0;
        o_sum[2] *= cr1; o_sum[3] *= cr1;

        // ---- O += Ph*Vh + Ph*Vl ; l += Ph*1 ----
        #pragma unroll
        for (int kk = 0; kk < 4; kk++) {
            uint32_t bv[4][4];
            const int rowv = kk * 16 + lrow;
            const uint32_t a0 = p0h[2 * kk], a1 = p1h[2 * kk];
            const uint32_t a2 = p0h[2 * kk + 1], a3 = p1h[2 * kk + 1];
            #pragma unroll
            for (int nb = 0; nb < 4; nb++)
                ldsm4t(bv[nb], Vsh + sw_off(rowv, nb * 32 + lcolb));
            #pragma unroll
            for (int nb = 0; nb < 4; nb++) {
                mma_hf(o[2 * nb],     a0, a1, a2, a3, bv[nb][0], bv[nb][1]);
                mma_hf(o[2 * nb + 1], a0, a1, a2, a3, bv[nb][2], bv[nb][3]);
            }
            mma_hf(o_sum, a0, a1, a2, a3, ONESH, ONESH);
            #pragma unroll
            for (int nb = 0; nb < 4; nb++)
                ldsm4t(bv[nb], Vsl + sw_off(rowv, nb * 32 + lcolb));
            #pragma unroll
            for (int nb = 0; nb < 4; nb++) {
                mma_hf(o[2 * nb],     a0, a1, a2, a3, bv[nb][0], bv[nb][1]);
                mma_hf(o[2 * nb + 1], a0, a1, a2, a3, bv[nb][2], bv[nb][3]);
            }
        }
        __syncthreads();
    }

    const float inv0 = 1.f / o_sum[0];
    const float inv1 = 1.f / o_sum[2];
    const int bb = bh >> 4, hh = bh & 15;
    #pragma unroll
    for (int nf = 0; nf < 8; nf++) {
        const int ch = hh * HD + nf * 8 + 2 * t;
        *(float2*)&out[((size_t)(bb * S_LEN + i0)) * D_MODEL + ch] =
            make_float2(o[nf][0] * inv0, o[nf][1] * inv0);
        *(float2*)&out[((size_t)(bb * S_LEN + i1)) * D_MODEL + ch] =
            make_float2(o[nf][2] * inv1, o[nf][3] * inv1);
    }
}

// ---------------------------------------------------------------------------
extern "C" void kernel_launch(void* const* d_in, const int* in_sizes, int n_in,
                              void* d_out, int out_size) {
    (void)in_sizes; (void)n_in; (void)out_size;
    const float* x    = (const float*)d_in[0];
    const float* Wqkv = (const float*)d_in[1];
    const float* bqkv = (const float*)d_in[2];
    const float* Wr   = (const float*)d_in[3];
    const float* br   = (const float*)d_in[4];
    float* out = (float*)d_out;

    uint32_t* xp; cudaGetSymbolAddress((void**)&xp, g_Xp);
    uint32_t* wp; cudaGetSymbolAddress((void**)&wp, g_Wp);
    split_kernel<<<(4096 * 1024 / 4 + 255) / 256, 256>>>(x, xp, 4096 * 1024 / 4);
    split_kernel<<<(3072 * 1024 / 4 + 255) / 256, 256>>>(Wqkv, wp, 3072 * 1024 / 4);
    wr_split_kernel<<<32, 256>>>(Wr);

    cudaFuncSetAttribute(qkv_mma_kernel, cudaFuncAttributeMaxDynamicSharedMemorySize,
                         QKV_SMEM_B);
    qkv_mma_kernel<<<768, 256, QKV_SMEM_B>>>(bqkv);

    cudaFuncSetAttribute(rp_mma_kernel, cudaFuncAttributeMaxDynamicSharedMemorySize,
                         RP_SMEM_B);
    dim3 g2(32, 32);
    rp_mma_kernel<<<g2, 256, RP_SMEM_B>>>(Wr, br);

    cudaFuncSetAttribute(attn_mma_kernel, cudaFuncAttributeMaxDynamicSharedMemorySize,
                         ATT_SMEM_B);
    dim3 g3(16, 32);
    attn_mma_kernel<<<g3, 256, ATT_SMEM_B>>>(out);
}